// round 2
// baseline (speedup 1.0000x reference)
#include <cuda_runtime.h>
#include <cfloat>
#include <climits>
#include <math.h>

// Beam search step: P=32 prompts, D=8 beams, V=128000, S=2048.
// Ordering by alive_lp + log(p) == ordering by m = p * exp(alive_lp) (monotone),
// so the hot 131MB scan does 1 FMUL/element; logf only on ~2k finalists/prompt.

#define P_ 32
#define D_ 8
#define V_ 128000
#define S_ 2048
#define NBLK 16          // blocks per prompt in k1 (2 per beam)
#define CHUNK 64000      // elements per k1 block (V/2)
#define NCAND 2048       // NBLK * 8 warps * 16
#define NC0 256          // 2 blocks * 8 warps * 16 (beam-0 lists)
#define EOS_ID 2
#define MASK_INF 10000000.0f

// output layout (flat float32, tuple concat order)
#define OFF_ATTN 0
#define OFF_ASEQ 256
#define OFF_ALP  524544
#define OFF_FSEQ 524800
#define OFF_FLP  1049088

__device__ float g_cand_val[P_ * NCAND];
__device__ int   g_cand_idx[P_ * NCAND];
__device__ float g_c0_val[P_ * NC0];
__device__ int   g_c0_idx[P_ * NC0];
__device__ int4  g_desc[2 * P_ * D_];   // {buf(0=alive,1=fin), src_beam, token, subpos(-1 none)}

#define FULLM 0xffffffffu

// Warp-cooperative insertion into a shared sorted top-16 list (desc value, asc index).
__device__ __forceinline__ void topk_insert(float v, int idx, float& th, int& thi,
                                            volatile float* lv, volatile int* li) {
    int lane = threadIdx.x & 31;
    bool want = (v > th) || (v == th && idx < thi);
    while (true) {
        unsigned mask = __ballot_sync(FULLM, want);
        if (!mask) break;
        int leader = __ffs(mask) - 1;
        if (lane == leader) {
            int pos = 16;
            for (int j = 15; j >= 0; j--) {
                if ((v > lv[j]) || (v == lv[j] && idx < li[j])) pos = j; else break;
            }
            if (pos < 16) {
                for (int j = 15; j > pos; j--) { lv[j] = lv[j-1]; li[j] = li[j-1]; }
                lv[pos] = v; li[pos] = idx;
            }
            want = false;
        }
        __syncwarp();
        th = lv[15]; thi = li[15];
        want = want && ((v > th) || (v == th && idx < thi));
    }
}

// ---------------- Kernel 1: scan probs, collect per-warp top-16 candidates ----
__global__ void __launch_bounds__(256)
k1_scan(const float* __restrict__ probs, const float* __restrict__ alive_lp) {
    int blk = blockIdx.x;
    int p = blk >> 4;
    int b = blk & 15;
    int d = b >> 1;
    int half = b & 1;
    int t = threadIdx.x, w = t >> 5, lane = t & 31;

    __shared__ float sv[8][16];  __shared__ int si[8][16];
    __shared__ float sv0[8][16]; __shared__ int si0[8][16];
    if (lane < 16) {
        sv[w][lane] = -FLT_MAX;  si[w][lane] = INT_MAX;
        sv0[w][lane] = -FLT_MAX; si0[w][lane] = INT_MAX;
    }
    __syncwarp();

    float scale = expf(alive_lp[p * D_ + d]);
    const float4* b4 = (const float4*)(probs + (long)(p * D_ + d) * V_ + half * CHUNK);
    int fb0 = d * V_ + half * CHUNK;
    float th = -FLT_MAX; int thi = INT_MAX;
    float t0 = -FLT_MAX; int t0i = INT_MAX;
    bool do0 = (d == 0);

    for (int j = t; j < CHUNK / 4; j += 256) {
        float4 v = b4[j];
        int fb = fb0 + j * 4;
        topk_insert(v.x * scale, fb + 0, th, thi, sv[w], si[w]);
        topk_insert(v.y * scale, fb + 1, th, thi, sv[w], si[w]);
        topk_insert(v.z * scale, fb + 2, th, thi, sv[w], si[w]);
        topk_insert(v.w * scale, fb + 3, th, thi, sv[w], si[w]);
        if (do0) {   // raw p ordering == log p ordering for beam-0 "first" path
            topk_insert(v.x, fb + 0, t0, t0i, sv0[w], si0[w]);
            topk_insert(v.y, fb + 1, t0, t0i, sv0[w], si0[w]);
            topk_insert(v.z, fb + 2, t0, t0i, sv0[w], si0[w]);
            topk_insert(v.w, fb + 3, t0, t0i, sv0[w], si0[w]);
        }
    }
    __syncwarp();
    if (lane < 16) {
        int cb = p * NCAND + (b * 8 + w) * 16 + lane;
        g_cand_val[cb] = sv[w][lane];
        g_cand_idx[cb] = si[w][lane];
        if (do0) {
            int c0 = p * NC0 + (half * 8 + w) * 16 + lane;
            g_c0_val[c0] = sv0[w][lane];
            g_c0_idx[c0] = si0[w][lane];
        }
    }
}

// Merge 128 shared candidates into sorted top-16 (one warp).
__device__ __forceinline__ void warp_merge128(volatile float* svals, volatile int* sidx,
                                              volatile float* outv, volatile int* outi) {
    int lane = threadIdx.x & 31;
    float mv[4]; int mi[4];
#pragma unroll
    for (int c = 0; c < 4; c++) { mv[c] = svals[lane * 4 + c]; mi[c] = sidx[lane * 4 + c]; }
    for (int k = 0; k < 16; k++) {
        float bv = mv[0]; int bi = mi[0];
#pragma unroll
        for (int c = 1; c < 4; c++)
            if (mv[c] > bv || (mv[c] == bv && mi[c] < bi)) { bv = mv[c]; bi = mi[c]; }
#pragma unroll
        for (int off = 16; off; off >>= 1) {
            float ov = __shfl_xor_sync(FULLM, bv, off);
            int   oi = __shfl_xor_sync(FULLM, bi, off);
            if (ov > bv || (ov == bv && oi < bi)) { bv = ov; bi = oi; }
        }
        if (lane == 0) { outv[k] = bv; outi[k] = bi; }
#pragma unroll
        for (int c = 0; c < 4; c++)
            if (mv[c] == bv && mi[c] == bi) { mv[c] = -FLT_MAX; mi[c] = INT_MAX; }
    }
}

// ---------------- Kernel 2: reduce candidates, do beam-search selection ------
__global__ void __launch_bounds__(256)
k2_select(const float* __restrict__ alive_lp, const float* __restrict__ fin_lp,
          const int* __restrict__ still_prompt,
          const int* __restrict__ is_first,
          const int* __restrict__ cur_pos_p, float* __restrict__ out) {
    int p = blockIdx.x;
    int t = threadIdx.x, w = t >> 5, lane = t & 31;

    __shared__ float sv[8][16];  __shared__ int si[8][16];
    __shared__ float sv0[8][16]; __shared__ int si0[8][16];
    __shared__ float fv[16];  __shared__ int fi[16];
    __shared__ float fv0[16]; __shared__ int fi0[16];

    if (lane < 16) {
        sv[w][lane] = -FLT_MAX;  si[w][lane] = INT_MAX;
        sv0[w][lane] = -FLT_MAX; si0[w][lane] = INT_MAX;
    }
    __syncwarp();

    {   // main candidates: 2048, warp w scans 256
        float th = -FLT_MAX; int thi = INT_MAX;
        for (int j = lane; j < 256; j += 32) {
            int a = p * NCAND + w * 256 + j;
            topk_insert(g_cand_val[a], g_cand_idx[a], th, thi, sv[w], si[w]);
        }
    }
    {   // beam0 candidates: 256, warp w scans 32 (one per lane)
        float th = -FLT_MAX; int thi = INT_MAX;
        int a = p * NC0 + w * 32 + lane;
        topk_insert(g_c0_val[a], g_c0_idx[a], th, thi, sv0[w], si0[w]);
    }
    __syncthreads();
    if (w == 0) warp_merge128(&sv[0][0],  &si[0][0],  fv,  fi);
    if (w == 1) warp_merge128(&sv0[0][0], &si0[0][0], fv0, fi0);
    __syncthreads();

    if (t == 0) {
        int cp = *cur_pos_p;
        bool sp = still_prompt[p] != 0;
        bool first = is_first[p] != 0;

        float lp16[16]; int tok16[16], beam16[16]; bool fin16[16];
        for (int k = 0; k < 16; k++) {
            int idx = fi[k];
            int bm = idx / V_;
            beam16[k] = bm;
            tok16[k]  = idx - bm * V_;
            lp16[k]   = logf(fv[k]);          // log(p*e^a) == a + log p
        }
        if (first) {
            float al0 = alive_lp[p * D_];
            for (int k = 0; k < 16; k++) {
                tok16[k] = fi0[k];            // flat idx within beam 0 == token
                lp16[k]  = al0 + logf(fv0[k]);
            }
        }
        for (int k = 0; k < 16; k++) fin16[k] = (tok16[k] == EOS_ID);

        // alive: top-8 of lp + finished*(-1e7)
        float am[16];
        for (int k = 0; k < 16; k++) am[k] = lp16[k] + (fin16[k] ? -MASK_INF : 0.0f);
        int na[8]; float nav[8]; bool used[16];
        for (int k = 0; k < 16; k++) used[k] = false;
        for (int j = 0; j < 8; j++) {
            int bi = -1; float bv = 0.0f;
            for (int k = 0; k < 16; k++)
                if (!used[k] && (bi < 0 || am[k] > bv)) { bi = k; bv = am[k]; }
            used[bi] = true; na[j] = bi; nav[j] = bv;
        }

        // finished: top-8 of [fin_lp(8), lp + !finished*(-1e7) (16)]
        float cl[24];
        for (int j = 0; j < 8; j++) cl[j] = fin_lp[p * D_ + j];
        for (int k = 0; k < 16; k++) cl[8 + k] = lp16[k] + (fin16[k] ? 0.0f : -MASK_INF);
        int nf[8]; float nfv[8]; bool used2[24];
        for (int k = 0; k < 24; k++) used2[k] = false;
        for (int j = 0; j < 8; j++) {
            int bi = -1; float bv = 0.0f;
            for (int k = 0; k < 24; k++)
                if (!used2[k] && (bi < 0 || cl[k] > bv)) { bi = k; bv = cl[k]; }
            used2[bi] = true; nf[j] = bi; nfv[j] = bv;
        }

        for (int j = 0; j < 8; j++) {
            out[OFF_ATTN + p * D_ + j] = sp ? (float)j : (float)beam16[na[j]];
            out[OFF_ALP  + p * D_ + j] = sp ? alive_lp[p * D_ + j] : nav[j];
            out[OFF_FLP  + p * D_ + j] = sp ? fin_lp[p * D_ + j]   : nfv[j];

            int4 da, df;
            if (sp) {
                da = make_int4(0, j, 0, -1);
                df = make_int4(1, j, 0, -1);
            } else {
                da = make_int4(0, beam16[na[j]], tok16[na[j]], cp);
                if (nf[j] < 8) df = make_int4(1, nf[j], 0, -1);
                else { int k = nf[j] - 8; df = make_int4(0, beam16[k], tok16[k], cp); }
            }
            g_desc[p * D_ + j] = da;
            g_desc[P_ * D_ + p * D_ + j] = df;
        }
    }
}

// ---------------- Kernel 3: gather output sequences --------------------------
__global__ void __launch_bounds__(256)
k3_gather(const int* __restrict__ alive_seq, const int* __restrict__ fin_seq,
          float* __restrict__ out) {
    int r = blockIdx.x;                       // 0..511
    int4 dsc = g_desc[r];
    bool isAlive = r < P_ * D_;
    int rr = isAlive ? r : r - P_ * D_;
    int p = rr >> 3;
    const int* srcbase = (dsc.x ? fin_seq : alive_seq) + (long)(p * D_ + dsc.y) * S_;
    long dst = (isAlive ? (long)OFF_ASEQ : (long)OFF_FSEQ) + (long)rr * S_;
    const int4* s4 = (const int4*)srcbase;
    float4* o4 = (float4*)(out + dst);
    int subpos = dsc.w, tok = dsc.z;
    for (int j = threadIdx.x; j < S_ / 4; j += 256) {
        int4 v = s4[j];
        int base = j * 4;
        if (subpos >= base && subpos < base + 4) {
            int* vp = (int*)&v;
            vp[subpos - base] = tok;
        }
        o4[j] = make_float4((float)v.x, (float)v.y, (float)v.z, (float)v.w);
    }
}

extern "C" void kernel_launch(void* const* d_in, const int* in_sizes, int n_in,
                              void* d_out, int out_size) {
    const float* probs        = (const float*)d_in[0];
    const int*   alive_seq    = (const int*)d_in[1];
    const int*   fin_seq      = (const int*)d_in[2];
    const float* alive_lp     = (const float*)d_in[3];
    const float* fin_lp       = (const float*)d_in[4];
    const int*   still_prompt = (const int*)d_in[5];
    const int*   is_first     = (const int*)d_in[6];
    const int*   cur_pos      = (const int*)d_in[7];
    float* out = (float*)d_out;

    k1_scan<<<P_ * NBLK, 256>>>(probs, alive_lp);
    k2_select<<<P_, 256>>>(alive_lp, fin_lp, still_prompt, is_first, cur_pos, out);
    k3_gather<<<2 * P_ * D_, 256>>>(alive_seq, fin_seq, out);
}

// round 3
// speedup vs baseline: 1.0186x; 1.0186x over previous
#include <cuda_runtime.h>
#include <cfloat>
#include <climits>
#include <math.h>

// Beam search step: P=32 prompts, D=8 beams, V=128000, S=2048.
// Ordering by alive_lp + log(p) == ordering by m = p * exp(alive_lp) (monotone),
// so the hot 131MB scan does 1 FMUL/element; logf only on ~2k finalists/prompt.

#define P_ 32
#define D_ 8
#define V_ 128000
#define S_ 2048
#define NBLK 16          // blocks per prompt in k1 (2 per beam)
#define CHUNK 64000      // elements per k1 block (V/2)
#define NCAND 2048       // NBLK * 8 warps * 16
#define NC0 256          // 2 blocks * 8 warps * 16 (beam-0 lists)
#define EOS_ID 2
#define MASK_INF 10000000.0f

// output layout (flat float32, tuple concat order)
#define OFF_ATTN 0
#define OFF_ASEQ 256
#define OFF_ALP  524544
#define OFF_FSEQ 524800
#define OFF_FLP  1049088

__device__ float g_cand_val[P_ * NCAND];
__device__ int   g_cand_idx[P_ * NCAND];
__device__ float g_c0_val[P_ * NC0];
__device__ int   g_c0_idx[P_ * NC0];
__device__ int4  g_desc[2 * P_ * D_];   // {buf(0=alive,1=fin), src_beam, token, subpos(-1 none)}

#define FULLM 0xffffffffu

// Warp-cooperative insertion into a shared sorted top-16 list (desc value, asc index).
__device__ __forceinline__ void topk_insert(float v, int idx, float& th, int& thi,
                                            volatile float* lv, volatile int* li) {
    int lane = threadIdx.x & 31;
    bool want = (v > th) || (v == th && idx < thi);
    while (true) {
        unsigned mask = __ballot_sync(FULLM, want);
        if (!mask) break;
        int leader = __ffs(mask) - 1;
        if (lane == leader) {
            int pos = 16;
            for (int j = 15; j >= 0; j--) {
                if ((v > lv[j]) || (v == lv[j] && idx < li[j])) pos = j; else break;
            }
            if (pos < 16) {
                for (int j = 15; j > pos; j--) { lv[j] = lv[j-1]; li[j] = li[j-1]; }
                lv[pos] = v; li[pos] = idx;
            }
            want = false;
        }
        __syncwarp();
        th = lv[15]; thi = li[15];
        want = want && ((v > th) || (v == th && idx < thi));
    }
}

// ---------------- Kernel 1: scan probs, collect per-warp top-16 candidates ----
__global__ void __launch_bounds__(256)
k1_scan(const float* __restrict__ probs, const float* __restrict__ alive_lp) {
    int blk = blockIdx.x;
    int p = blk >> 4;
    int b = blk & 15;
    int d = b >> 1;
    int half = b & 1;
    int t = threadIdx.x, w = t >> 5, lane = t & 31;

    __shared__ float sv[8][16];  __shared__ int si[8][16];
    __shared__ float sv0[8][16]; __shared__ int si0[8][16];
    if (lane < 16) {
        sv[w][lane] = -FLT_MAX;  si[w][lane] = INT_MAX;
        sv0[w][lane] = -FLT_MAX; si0[w][lane] = INT_MAX;
    }
    __syncwarp();

    float scale = expf(alive_lp[p * D_ + d]);
    const float4* b4 = (const float4*)(probs + (long)(p * D_ + d) * V_ + half * CHUNK);
    int fb0 = d * V_ + half * CHUNK;
    float th = -FLT_MAX; int thi = INT_MAX;
    float t0 = -FLT_MAX; int t0i = INT_MAX;
    bool do0 = (d == 0);

    for (int j = t; j < CHUNK / 4; j += 256) {
        float4 v = b4[j];
        int fb = fb0 + j * 4;
        topk_insert(v.x * scale, fb + 0, th, thi, sv[w], si[w]);
        topk_insert(v.y * scale, fb + 1, th, thi, sv[w], si[w]);
        topk_insert(v.z * scale, fb + 2, th, thi, sv[w], si[w]);
        topk_insert(v.w * scale, fb + 3, th, thi, sv[w], si[w]);
        if (do0) {   // raw p ordering == log p ordering for beam-0 "first" path
            topk_insert(v.x, fb + 0, t0, t0i, sv0[w], si0[w]);
            topk_insert(v.y, fb + 1, t0, t0i, sv0[w], si0[w]);
            topk_insert(v.z, fb + 2, t0, t0i, sv0[w], si0[w]);
            topk_insert(v.w, fb + 3, t0, t0i, sv0[w], si0[w]);
        }
    }
    __syncwarp();
    if (lane < 16) {
        int cb = p * NCAND + (b * 8 + w) * 16 + lane;
        g_cand_val[cb] = sv[w][lane];
        g_cand_idx[cb] = si[w][lane];
        if (do0) {
            int c0 = p * NC0 + (half * 8 + w) * 16 + lane;
            g_c0_val[c0] = sv0[w][lane];
            g_c0_idx[c0] = si0[w][lane];
        }
    }
}

// Merge 128 shared candidates into sorted top-16 (one warp).
__device__ __forceinline__ void warp_merge128(volatile float* svals, volatile int* sidx,
                                              volatile float* outv, volatile int* outi) {
    int lane = threadIdx.x & 31;
    float mv[4]; int mi[4];
#pragma unroll
    for (int c = 0; c < 4; c++) { mv[c] = svals[lane * 4 + c]; mi[c] = sidx[lane * 4 + c]; }
    for (int k = 0; k < 16; k++) {
        float bv = mv[0]; int bi = mi[0];
#pragma unroll
        for (int c = 1; c < 4; c++)
            if (mv[c] > bv || (mv[c] == bv && mi[c] < bi)) { bv = mv[c]; bi = mi[c]; }
#pragma unroll
        for (int off = 16; off; off >>= 1) {
            float ov = __shfl_xor_sync(FULLM, bv, off);
            int   oi = __shfl_xor_sync(FULLM, bi, off);
            if (ov > bv || (ov == bv && oi < bi)) { bv = ov; bi = oi; }
        }
        if (lane == 0) { outv[k] = bv; outi[k] = bi; }
#pragma unroll
        for (int c = 0; c < 4; c++)
            if (mv[c] == bv && mi[c] == bi) { mv[c] = -FLT_MAX; mi[c] = INT_MAX; }
    }
}

// ---------------- Kernel 2: reduce candidates, do beam-search selection ------
__global__ void __launch_bounds__(256)
k2_select(const float* __restrict__ alive_lp, const float* __restrict__ fin_lp,
          const int* __restrict__ still_prompt,
          const int* __restrict__ is_first,
          const int* __restrict__ cur_pos_p, float* __restrict__ out) {
    int p = blockIdx.x;
    int t = threadIdx.x, w = t >> 5, lane = t & 31;

    __shared__ float sv[8][16];  __shared__ int si[8][16];
    __shared__ float sv0[8][16]; __shared__ int si0[8][16];
    __shared__ float fv[16];  __shared__ int fi[16];
    __shared__ float fv0[16]; __shared__ int fi0[16];

    if (lane < 16) {
        sv[w][lane] = -FLT_MAX;  si[w][lane] = INT_MAX;
        sv0[w][lane] = -FLT_MAX; si0[w][lane] = INT_MAX;
    }
    __syncwarp();

    {   // main candidates: 2048, warp w scans 256
        float th = -FLT_MAX; int thi = INT_MAX;
        for (int j = lane; j < 256; j += 32) {
            int a = p * NCAND + w * 256 + j;
            topk_insert(g_cand_val[a], g_cand_idx[a], th, thi, sv[w], si[w]);
        }
    }
    {   // beam0 candidates: 256, warp w scans 32 (one per lane)
        float th = -FLT_MAX; int thi = INT_MAX;
        int a = p * NC0 + w * 32 + lane;
        topk_insert(g_c0_val[a], g_c0_idx[a], th, thi, sv0[w], si0[w]);
    }
    __syncthreads();
    if (w == 0) warp_merge128(&sv[0][0],  &si[0][0],  fv,  fi);
    if (w == 1) warp_merge128(&sv0[0][0], &si0[0][0], fv0, fi0);
    __syncthreads();

    if (t == 0) {
        int cp = *cur_pos_p;
        bool sp = still_prompt[p] != 0;
        bool first = is_first[p] != 0;

        float lp16[16]; int tok16[16], beam16[16]; bool fin16[16];
        for (int k = 0; k < 16; k++) {
            int idx = fi[k];
            int bm = idx / V_;
            beam16[k] = bm;
            tok16[k]  = idx - bm * V_;
            lp16[k]   = logf(fv[k]);          // log(p*e^a) == a + log p
        }
        if (first) {
            float al0 = alive_lp[p * D_];
            for (int k = 0; k < 16; k++) {
                tok16[k] = fi0[k];            // flat idx within beam 0 == token
                lp16[k]  = al0 + logf(fv0[k]);
            }
        }
        for (int k = 0; k < 16; k++) fin16[k] = (tok16[k] == EOS_ID);

        // alive: top-8 of lp + finished*(-1e7)
        float am[16];
        for (int k = 0; k < 16; k++) am[k] = lp16[k] + (fin16[k] ? -MASK_INF : 0.0f);
        int na[8]; float nav[8]; bool used[16];
        for (int k = 0; k < 16; k++) used[k] = false;
        for (int j = 0; j < 8; j++) {
            int bi = -1; float bv = 0.0f;
            for (int k = 0; k < 16; k++)
                if (!used[k] && (bi < 0 || am[k] > bv)) { bi = k; bv = am[k]; }
            used[bi] = true; na[j] = bi; nav[j] = bv;
        }

        // finished: top-8 of [fin_lp(8), lp + !finished*(-1e7) (16)]
        float cl[24];
        for (int j = 0; j < 8; j++) cl[j] = fin_lp[p * D_ + j];
        for (int k = 0; k < 16; k++) cl[8 + k] = lp16[k] + (fin16[k] ? 0.0f : -MASK_INF);
        int nf[8]; float nfv[8]; bool used2[24];
        for (int k = 0; k < 24; k++) used2[k] = false;
        for (int j = 0; j < 8; j++) {
            int bi = -1; float bv = 0.0f;
            for (int k = 0; k < 24; k++)
                if (!used2[k] && (bi < 0 || cl[k] > bv)) { bi = k; bv = cl[k]; }
            used2[bi] = true; nf[j] = bi; nfv[j] = bv;
        }

        for (int j = 0; j < 8; j++) {
            out[OFF_ATTN + p * D_ + j] = sp ? (float)j : (float)beam16[na[j]];
            out[OFF_ALP  + p * D_ + j] = sp ? alive_lp[p * D_ + j] : nav[j];
            out[OFF_FLP  + p * D_ + j] = sp ? fin_lp[p * D_ + j]   : nfv[j];

            int4 da, df;
            if (sp) {
                da = make_int4(0, j, 0, -1);
                df = make_int4(1, j, 0, -1);
            } else {
                da = make_int4(0, beam16[na[j]], tok16[na[j]], cp);
                if (nf[j] < 8) df = make_int4(1, nf[j], 0, -1);
                else { int k = nf[j] - 8; df = make_int4(0, beam16[k], tok16[k], cp); }
            }
            g_desc[p * D_ + j] = da;
            g_desc[P_ * D_ + p * D_ + j] = df;
        }
    }
}

// ---------------- Kernel 3: gather output sequences --------------------------
__global__ void __launch_bounds__(256)
k3_gather(const int* __restrict__ alive_seq, const int* __restrict__ fin_seq,
          float* __restrict__ out) {
    int r = blockIdx.x;                       // 0..511
    int4 dsc = g_desc[r];
    bool isAlive = r < P_ * D_;
    int rr = isAlive ? r : r - P_ * D_;
    int p = rr >> 3;
    const int* srcbase = (dsc.x ? fin_seq : alive_seq) + (long)(p * D_ + dsc.y) * S_;
    long dst = (isAlive ? (long)OFF_ASEQ : (long)OFF_FSEQ) + (long)rr * S_;
    const int4* s4 = (const int4*)srcbase;
    float4* o4 = (float4*)(out + dst);
    int subpos = dsc.w, tok = dsc.z;
    for (int j = threadIdx.x; j < S_ / 4; j += 256) {
        int4 v = s4[j];
        int base = j * 4;
        if (subpos >= base && subpos < base + 4) {
            int* vp = (int*)&v;
            vp[subpos - base] = tok;
        }
        o4[j] = make_float4((float)v.x, (float)v.y, (float)v.z, (float)v.w);
    }
}

extern "C" void kernel_launch(void* const* d_in, const int* in_sizes, int n_in,
                              void* d_out, int out_size) {
    const float* probs        = (const float*)d_in[0];
    const int*   alive_seq    = (const int*)d_in[1];
    const int*   fin_seq      = (const int*)d_in[2];
    const float* alive_lp     = (const float*)d_in[3];
    const float* fin_lp       = (const float*)d_in[4];
    const int*   still_prompt = (const int*)d_in[5];
    const int*   is_first     = (const int*)d_in[6];
    const int*   cur_pos      = (const int*)d_in[7];
    float* out = (float*)d_out;

    k1_scan<<<P_ * NBLK, 256>>>(probs, alive_lp);
    k2_select<<<P_, 256>>>(alive_lp, fin_lp, still_prompt, is_first, cur_pos, out);
    k3_gather<<<2 * P_ * D_, 256>>>(alive_seq, fin_seq, out);
}